// round 2
// baseline (speedup 1.0000x reference)
#include <cuda_runtime.h>
#include <math.h>

// Problem constants
constexpr int PB = 2;      // batch
constexpr int PT = 2048;   // query seq
constexpr int PS = 2048;   // key/value seq
constexpr int PD = 1024;   // model dim
constexpr int PH = 16;     // heads
constexpr int PDK = 64;    // head dim

// ---------------------------------------------------------------------------
// Scratch (device globals — no allocation allowed)
// ---------------------------------------------------------------------------
__device__ float g_q[(size_t)PB * PH * PT * PDK];   // (B,H,T,DK)
__device__ float g_k[(size_t)PB * PH * PS * PDK];   // (B,H,S,DK)
__device__ float g_v[(size_t)PB * PH * PS * PDK];   // (B,H,S,DK)
__device__ float g_attn[(size_t)PB * PT * PD];      // (B,T,H*DK)

constexpr int BM = 128, BN = 128, BK = 16;

// Projection GEMM: C = A(MxK)*W(KxN)+bias, stored as ((b*H+h)*SEQ+t)*DK+dk
__global__ __launch_bounds__(256) void proj_gemm_kernel(
    const float* __restrict__ A, const float* __restrict__ W,
    const float* __restrict__ bias, float* __restrict__ Cout,
    int M, int N, int K)
{
    __shared__ float As[BK][BM + 4];
    __shared__ float Bs[BK][BN];

    const int tid = threadIdx.x;
    const int tx = tid & 15;
    const int ty = tid >> 4;
    const int bm = blockIdx.y * BM;
    const int bn = blockIdx.x * BN;

    const int aCol = (tid & 3) * 4;
    const int aRow = tid >> 2;
    const int bCol = (tid & 31) * 4;
    const int bRow = tid >> 5;

    float acc[8][8];
#pragma unroll
    for (int i = 0; i < 8; i++)
#pragma unroll
        for (int j = 0; j < 8; j++) acc[i][j] = 0.f;

    for (int k0 = 0; k0 < K; k0 += BK) {
#pragma unroll
        for (int p = 0; p < 2; p++) {
            int r = aRow + p * 64;
            float4 av = *(const float4*)(A + (size_t)(bm + r) * K + k0 + aCol);
            As[aCol + 0][r] = av.x;
            As[aCol + 1][r] = av.y;
            As[aCol + 2][r] = av.z;
            As[aCol + 3][r] = av.w;
        }
#pragma unroll
        for (int p = 0; p < 2; p++) {
            int r = bRow + p * 8;
            *(float4*)&Bs[r][bCol] =
                *(const float4*)(W + (size_t)(k0 + r) * N + bn + bCol);
        }
        __syncthreads();

#pragma unroll
        for (int kk = 0; kk < BK; kk++) {
            float ra[8], rb[8];
            *(float4*)&ra[0] = *(float4*)&As[kk][ty * 8];
            *(float4*)&ra[4] = *(float4*)&As[kk][ty * 8 + 4];
            *(float4*)&rb[0] = *(float4*)&Bs[kk][tx * 8];
            *(float4*)&rb[4] = *(float4*)&Bs[kk][tx * 8 + 4];
#pragma unroll
            for (int i = 0; i < 8; i++)
#pragma unroll
                for (int j = 0; j < 8; j++)
                    acc[i][j] += ra[i] * rb[j];
        }
        __syncthreads();
    }

    const int col0 = bn + tx * 8;
    const int h = col0 / PDK;
    const int dk = col0 - h * PDK;   // 8 cols stay within one head (8 | 64)
#pragma unroll
    for (int i = 0; i < 8; i++) {
        int row = bm + ty * 8 + i;
        int b = row / PT;
        int t = row - b * PT;
        size_t base = (((size_t)(b * PH + h) * PT) + t) * PDK + dk;
#pragma unroll
        for (int j = 0; j < 8; j++)
            Cout[base + j] = acc[i][j] + bias[col0 + j];
    }
}

// Plain GEMM: C[row*N+col] = A*W + bias
__global__ __launch_bounds__(256) void plain_gemm_kernel(
    const float* __restrict__ A, const float* __restrict__ W,
    const float* __restrict__ bias, float* __restrict__ C,
    int M, int N, int K)
{
    __shared__ float As[BK][BM + 4];
    __shared__ float Bs[BK][BN];

    const int tid = threadIdx.x;
    const int tx = tid & 15;
    const int ty = tid >> 4;
    const int bm = blockIdx.y * BM;
    const int bn = blockIdx.x * BN;

    const int aCol = (tid & 3) * 4;
    const int aRow = tid >> 2;
    const int bCol = (tid & 31) * 4;
    const int bRow = tid >> 5;

    float acc[8][8];
#pragma unroll
    for (int i = 0; i < 8; i++)
#pragma unroll
        for (int j = 0; j < 8; j++) acc[i][j] = 0.f;

    for (int k0 = 0; k0 < K; k0 += BK) {
#pragma unroll
        for (int p = 0; p < 2; p++) {
            int r = aRow + p * 64;
            float4 av = *(const float4*)(A + (size_t)(bm + r) * K + k0 + aCol);
            As[aCol + 0][r] = av.x;
            As[aCol + 1][r] = av.y;
            As[aCol + 2][r] = av.z;
            As[aCol + 3][r] = av.w;
        }
#pragma unroll
        for (int p = 0; p < 2; p++) {
            int r = bRow + p * 8;
            *(float4*)&Bs[r][bCol] =
                *(const float4*)(W + (size_t)(k0 + r) * N + bn + bCol);
        }
        __syncthreads();

#pragma unroll
        for (int kk = 0; kk < BK; kk++) {
            float ra[8], rb[8];
            *(float4*)&ra[0] = *(float4*)&As[kk][ty * 8];
            *(float4*)&ra[4] = *(float4*)&As[kk][ty * 8 + 4];
            *(float4*)&rb[0] = *(float4*)&Bs[kk][tx * 8];
            *(float4*)&rb[4] = *(float4*)&Bs[kk][tx * 8 + 4];
#pragma unroll
            for (int i = 0; i < 8; i++)
#pragma unroll
                for (int j = 0; j < 8; j++)
                    acc[i][j] += ra[i] * rb[j];
        }
        __syncthreads();
    }

    const int col0 = bn + tx * 8;
#pragma unroll
    for (int i = 0; i < 8; i++) {
        int row = bm + ty * 8 + i;
        float* dst = C + (size_t)row * N + col0;
#pragma unroll
        for (int j = 0; j < 8; j++) dst[j] = acc[i][j] + bias[col0 + j];
    }
}

// ---------------------------------------------------------------------------
// Flash attention (fp32, online softmax)
// ---------------------------------------------------------------------------
constexpr int ABR = 64, ABC = 64, APAD = 68;
constexpr int ATTN_SMEM = 3 * 64 * APAD * 4;

__global__ __launch_bounds__(128) void attn_kernel(
    const float* __restrict__ q, const float* __restrict__ k,
    const float* __restrict__ v, float* __restrict__ o)
{
    extern __shared__ float sm[];
    float* Qs = sm;                  // [64][APAD]
    float* Ks = sm + 64 * APAD;      // [64][APAD], reused as P tile
    float* Vt = sm + 2 * 64 * APAD;  // [64(d)][APAD] transposed V

    const int tid = threadIdx.x;
    const int rg = tid >> 3;   // rows rg*4 .. rg*4+3
    const int cg = tid & 7;    // cols cg + 8*j
    const int t0 = blockIdx.x * ABR;
    const int h = blockIdx.y;
    const int b = blockIdx.z;

    const float* qb = q + (((size_t)(b * PH + h) * PT) + t0) * PDK;
    const float* kb = k + (size_t)(b * PH + h) * PS * PDK;
    const float* vb = v + (size_t)(b * PH + h) * PS * PDK;

    for (int idx = tid; idx < 64 * 16; idx += 128) {
        int r = idx >> 4;
        int c4 = (idx & 15) << 2;
        float4 qv = *(const float4*)(qb + r * PDK + c4);
        Qs[r * APAD + c4 + 0] = qv.x * 0.125f;
        Qs[r * APAD + c4 + 1] = qv.y * 0.125f;
        Qs[r * APAD + c4 + 2] = qv.z * 0.125f;
        Qs[r * APAD + c4 + 3] = qv.w * 0.125f;
    }

    float m[4], l[4], O[4][8];
#pragma unroll
    for (int i = 0; i < 4; i++) {
        m[i] = -1e30f;
        l[i] = 0.f;
#pragma unroll
        for (int j = 0; j < 8; j++) O[i][j] = 0.f;
    }

    for (int s0 = 0; s0 < PS; s0 += ABC) {
        for (int idx = tid; idx < 64 * 16; idx += 128) {
            int r = idx >> 4;
            int c4 = (idx & 15) << 2;
            *(float4*)&Ks[r * APAD + c4] =
                *(const float4*)(kb + (size_t)(s0 + r) * PDK + c4);
            float4 vv = *(const float4*)(vb + (size_t)(s0 + r) * PDK + c4);
            Vt[(c4 + 0) * APAD + r] = vv.x;
            Vt[(c4 + 1) * APAD + r] = vv.y;
            Vt[(c4 + 2) * APAD + r] = vv.z;
            Vt[(c4 + 3) * APAD + r] = vv.w;
        }
        __syncthreads();

        float sc[4][8];
#pragma unroll
        for (int i = 0; i < 4; i++)
#pragma unroll
            for (int j = 0; j < 8; j++) sc[i][j] = 0.f;

#pragma unroll
        for (int kk = 0; kk < 64; kk += 4) {
            float4 qv[4], kv[8];
#pragma unroll
            for (int i = 0; i < 4; i++)
                qv[i] = *(float4*)&Qs[(rg * 4 + i) * APAD + kk];
#pragma unroll
            for (int j = 0; j < 8; j++)
                kv[j] = *(float4*)&Ks[(cg + 8 * j) * APAD + kk];
#pragma unroll
            for (int i = 0; i < 4; i++)
#pragma unroll
                for (int j = 0; j < 8; j++) {
                    sc[i][j] += qv[i].x * kv[j].x;
                    sc[i][j] += qv[i].y * kv[j].y;
                    sc[i][j] += qv[i].z * kv[j].z;
                    sc[i][j] += qv[i].w * kv[j].w;
                }
        }
        __syncthreads();

        float* Ps = Ks;
#pragma unroll
        for (int i = 0; i < 4; i++) {
            float mx = sc[i][0];
#pragma unroll
            for (int j = 1; j < 8; j++) mx = fmaxf(mx, sc[i][j]);
            mx = fmaxf(mx, __shfl_xor_sync(0xFFFFFFFFu, mx, 1));
            mx = fmaxf(mx, __shfl_xor_sync(0xFFFFFFFFu, mx, 2));
            mx = fmaxf(mx, __shfl_xor_sync(0xFFFFFFFFu, mx, 4));
            float mn = fmaxf(m[i], mx);
            float corr = __expf(m[i] - mn);
            float rs = 0.f;
#pragma unroll
            for (int j = 0; j < 8; j++) {
                float p = __expf(sc[i][j] - mn);
                sc[i][j] = p;
                rs += p;
            }
            rs += __shfl_xor_sync(0xFFFFFFFFu, rs, 1);
            rs += __shfl_xor_sync(0xFFFFFFFFu, rs, 2);
            rs += __shfl_xor_sync(0xFFFFFFFFu, rs, 4);
            l[i] = l[i] * corr + rs;
            m[i] = mn;
#pragma unroll
            for (int j = 0; j < 8; j++) O[i][j] *= corr;
#pragma unroll
            for (int j = 0; j < 8; j++)
                Ps[(rg * 4 + i) * APAD + cg + 8 * j] = sc[i][j];
        }
        __syncthreads();

#pragma unroll
        for (int ss = 0; ss < 64; ss += 4) {
            float4 pv[4], vv[8];
#pragma unroll
            for (int i = 0; i < 4; i++)
                pv[i] = *(float4*)&Ps[(rg * 4 + i) * APAD + ss];
#pragma unroll
            for (int j = 0; j < 8; j++)
                vv[j] = *(float4*)&Vt[(cg + 8 * j) * APAD + ss];
#pragma unroll
            for (int i = 0; i < 4; i++)
#pragma unroll
                for (int j = 0; j < 8; j++) {
                    O[i][j] += pv[i].x * vv[j].x;
                    O[i][j] += pv[i].y * vv[j].y;
                    O[i][j] += pv[i].z * vv[j].z;
                    O[i][j] += pv[i].w * vv[j].w;
                }
        }
        __syncthreads();
    }

#pragma unroll
    for (int i = 0; i < 4; i++) {
        float inv = 1.0f / l[i];
        int t = t0 + rg * 4 + i;
        size_t base = ((size_t)(b * PT + t)) * PD + h * PDK;
#pragma unroll
        for (int j = 0; j < 8; j++)
            o[base + cg + 8 * j] = O[i][j] * inv;
    }
}

// ---------------------------------------------------------------------------
extern "C" void kernel_launch(void* const* d_in, const int* in_sizes, int n_in,
                              void* d_out, int out_size)
{
    const float* query = (const float*)d_in[0];
    const float* value = (const float*)d_in[1];
    const float* key   = (const float*)d_in[2];
    const float* Wq    = (const float*)d_in[3];
    const float* bq    = (const float*)d_in[4];
    const float* Wk    = (const float*)d_in[5];
    const float* bk    = (const float*)d_in[6];
    const float* Wv    = (const float*)d_in[7];
    const float* bv    = (const float*)d_in[8];
    const float* Wo    = (const float*)d_in[9];
    const float* bo    = (const float*)d_in[10];
    float* out = (float*)d_out;

    float *gq, *gk, *gv, *ga;
    cudaGetSymbolAddress((void**)&gq, g_q);
    cudaGetSymbolAddress((void**)&gk, g_k);
    cudaGetSymbolAddress((void**)&gv, g_v);
    cudaGetSymbolAddress((void**)&ga, g_attn);

    const int M = PB * PT;   // 4096
    const int N = PD;        // 1024
    const int K = PD;        // 1024
    dim3 ggrid(N / BN, M / BM);  // (8, 32)

    proj_gemm_kernel<<<ggrid, 256>>>(query, Wq, bq, gq, M, N, K);
    proj_gemm_kernel<<<ggrid, 256>>>(key,   Wk, bk, gk, M, N, K);
    proj_gemm_kernel<<<ggrid, 256>>>(value, Wv, bv, gv, M, N, K);

    cudaFuncSetAttribute(attn_kernel,
                         cudaFuncAttributeMaxDynamicSharedMemorySize,
                         ATTN_SMEM);
    attn_kernel<<<dim3(PT / ABR, PH, PB), 128, ATTN_SMEM>>>(gq, gk, gv, ga);

    plain_gemm_kernel<<<ggrid, 256>>>(ga, Wo, bo, out, M, N, K);
}

// round 4
// speedup vs baseline: 1.2959x; 1.2959x over previous
#include <cuda_runtime.h>
#include <cuda_bf16.h>
#include <math.h>
#include <stdint.h>

// Problem constants
constexpr int PB = 2;      // batch
constexpr int PT = 2048;   // query seq
constexpr int PS = 2048;   // key/value seq
constexpr int PD = 1024;   // model dim
constexpr int PH = 16;     // heads
constexpr int PDK = 64;    // head dim

constexpr int GEMM_M = PB * PT;  // 4096
constexpr int GEMM_N = PD;       // 1024
constexpr int GEMM_K = PD;       // 1024

// ---------------------------------------------------------------------------
// Scratch (device globals — no allocation allowed)
// ---------------------------------------------------------------------------
__device__ float g_q[(size_t)PB * PH * PT * PDK];   // (B,H,T,DK)
__device__ float g_k[(size_t)PB * PH * PS * PDK];   // (B,H,S,DK)
__device__ float g_v[(size_t)PB * PH * PS * PDK];   // (B,H,S,DK)
__device__ float g_attn[(size_t)PB * PT * PD];      // (B,T,H*DK)

// bf16 hi/lo split buffers (reused across sequential GEMMs)
__device__ __nv_bfloat16 g_ahi[(size_t)GEMM_M * GEMM_K];
__device__ __nv_bfloat16 g_alo[(size_t)GEMM_M * GEMM_K];
__device__ __nv_bfloat16 g_bhi[(size_t)GEMM_N * GEMM_K];  // W^T, K-major per n
__device__ __nv_bfloat16 g_blo[(size_t)GEMM_N * GEMM_K];

// ---------------------------------------------------------------------------
// PTX helpers (base ISA only: mma.sync / ldmatrix / cp.async)
// ---------------------------------------------------------------------------
__device__ __forceinline__ uint32_t smem_u32(const void* p) {
    uint32_t a;
    asm("{ .reg .u64 t; cvta.to.shared.u64 t, %1; cvt.u32.u64 %0, t; }"
        : "=r"(a) : "l"(p));
    return a;
}

__device__ __forceinline__ void cp16(uint32_t saddr, const void* gaddr) {
    asm volatile("cp.async.cg.shared.global [%0], [%1], 16;"
                 :: "r"(saddr), "l"(gaddr) : "memory");
}
#define CP_COMMIT() asm volatile("cp.async.commit_group;" ::: "memory")
#define CP_WAIT1()  asm volatile("cp.async.wait_group 1;" ::: "memory")
#define CP_WAIT0()  asm volatile("cp.async.wait_group 0;" ::: "memory")

__device__ __forceinline__ void ldsm_x4(uint32_t& r0, uint32_t& r1,
                                        uint32_t& r2, uint32_t& r3,
                                        uint32_t addr) {
    asm volatile("ldmatrix.sync.aligned.m8n8.x4.shared.b16 {%0,%1,%2,%3}, [%4];"
                 : "=r"(r0), "=r"(r1), "=r"(r2), "=r"(r3) : "r"(addr));
}

__device__ __forceinline__ void mma_bf16(float* d, const uint32_t* a,
                                         const uint32_t* b) {
    asm volatile(
        "mma.sync.aligned.m16n8k16.row.col.f32.bf16.bf16.f32 "
        "{%0,%1,%2,%3}, {%4,%5,%6,%7}, {%8,%9}, {%0,%1,%2,%3};"
        : "+f"(d[0]), "+f"(d[1]), "+f"(d[2]), "+f"(d[3])
        : "r"(a[0]), "r"(a[1]), "r"(a[2]), "r"(a[3]),
          "r"(b[0]), "r"(b[1]));
}

// ---------------------------------------------------------------------------
// Split kernels: fp32 -> bf16 hi/lo
// ---------------------------------------------------------------------------
__global__ __launch_bounds__(256) void split_a_kernel(
    const float* __restrict__ x, __nv_bfloat16* __restrict__ hi,
    __nv_bfloat16* __restrict__ lo, int n4)
{
    int i = blockIdx.x * blockDim.x + threadIdx.x;
    if (i >= n4) return;
    float4 v = ((const float4*)x)[i];
    __nv_bfloat16 h0 = __float2bfloat16(v.x);
    __nv_bfloat16 h1 = __float2bfloat16(v.y);
    __nv_bfloat16 h2 = __float2bfloat16(v.z);
    __nv_bfloat16 h3 = __float2bfloat16(v.w);
    __nv_bfloat162* hp = (__nv_bfloat162*)hi;
    __nv_bfloat162* lp = (__nv_bfloat162*)lo;
    hp[2 * i + 0] = __nv_bfloat162(h0, h1);
    hp[2 * i + 1] = __nv_bfloat162(h2, h3);
    lp[2 * i + 0] = __nv_bfloat162(
        __float2bfloat16(v.x - __bfloat162float(h0)),
        __float2bfloat16(v.y - __bfloat162float(h1)));
    lp[2 * i + 1] = __nv_bfloat162(
        __float2bfloat16(v.z - __bfloat162float(h2)),
        __float2bfloat16(v.w - __bfloat162float(h3)));
}

// W[K][N] (row-major) -> B^T[N][K] bf16 hi/lo (K contiguous)
__global__ __launch_bounds__(256) void split_w_kernel(
    const float* __restrict__ W, __nv_bfloat16* __restrict__ hi,
    __nv_bfloat16* __restrict__ lo)
{
    __shared__ float t[32][33];
    int n0 = blockIdx.x * 32, k0 = blockIdx.y * 32;
    int tx = threadIdx.x, ty = threadIdx.y;   // block (32, 8)
#pragma unroll
    for (int i = 0; i < 32; i += 8)
        t[ty + i][tx] = W[(size_t)(k0 + ty + i) * GEMM_N + n0 + tx];
    __syncthreads();
#pragma unroll
    for (int i = 0; i < 32; i += 8) {
        float v = t[tx][ty + i];
        __nv_bfloat16 h = __float2bfloat16(v);
        size_t o = (size_t)(n0 + ty + i) * GEMM_K + k0 + tx;
        hi[o] = h;
        lo[o] = __float2bfloat16(v - __bfloat162float(h));
    }
}

// ---------------------------------------------------------------------------
// HMMA GEMM: C(4096x1024) = A x W + bias, bf16 hi/lo 3-pass, fp32 acc.
// Block 128x128, BK=32, 8 warps (4M x 2N), warp tile 32x64.
// Smem rows padded to 40 bf16 (80 B) -> conflict-free ldmatrix.
// ---------------------------------------------------------------------------
constexpr int MBK = 32;
constexpr int STR = 40;                         // padded row stride (bf16)
constexpr int TILE_B = 128 * STR * 2;           // 10240 bytes per tile
constexpr int STAGE_B = 4 * TILE_B;             // Ahi, Alo, Bhi, Blo
constexpr int GSM_TOTAL = 2 * STAGE_B;          // 81920
constexpr int NCHUNKS = GEMM_K / MBK;           // 32

__device__ __forceinline__ void load_tile32(
    uint32_t sdst, const __nv_bfloat16* __restrict__ g, int row0, int k0, int tid)
{
    // 128 rows x 32 bf16; 4 x 16B segs per row; 512 segs / 256 threads
#pragma unroll
    for (int i = 0; i < 2; i++) {
        int s = tid + i * 256;
        int r = s >> 2;
        int c = s & 3;
        cp16(sdst + (uint32_t)(r * (STR * 2) + c * 16),
             g + (size_t)(row0 + r) * GEMM_K + k0 + c * 8);
    }
}

template <int MODE>
__global__ __launch_bounds__(256, 1) void tc_gemm_kernel(
    const __nv_bfloat16* __restrict__ Ahi, const __nv_bfloat16* __restrict__ Alo,
    const __nv_bfloat16* __restrict__ Bhi, const __nv_bfloat16* __restrict__ Blo,
    const float* __restrict__ bias, float* __restrict__ C)
{
    extern __shared__ __align__(128) char smem[];
    const uint32_t sb = smem_u32(smem);
    const int tid = threadIdx.x;
    const int wid = tid >> 5;
    const int lane = tid & 31;
    const int wm = wid >> 1;        // 0..3  (32-row slice)
    const int wn = wid & 1;         // 0..1  (64-col slice)
    const int bm = blockIdx.y * 128;
    const int bn = blockIdx.x * 128;

    float acc[2][8][4];
#pragma unroll
    for (int i = 0; i < 2; i++)
#pragma unroll
        for (int j = 0; j < 8; j++)
#pragma unroll
            for (int r = 0; r < 4; r++) acc[i][j][r] = 0.f;

    // Precomputed ldmatrix lane offsets (bytes), within a tile
    // A: row = base + ((lane>>3)&1)*8 + (lane&7), col = (lane>>4)*8
    const int a_r = ((lane >> 3) & 1) * 8 + (lane & 7);
    const int a_c = (lane >> 4) * 8;
    // B pair: row = base + (lane>>4)*8 + (lane&7), col = ((lane>>3)&1)*8
    const int b_r = (lane >> 4) * 8 + (lane & 7);
    const int b_c = ((lane >> 3) & 1) * 8;

    // Prologue: stage 0
    {
        uint32_t st = sb;
        load_tile32(st + 0 * TILE_B, Ahi, bm, 0, tid);
        load_tile32(st + 1 * TILE_B, Alo, bm, 0, tid);
        load_tile32(st + 2 * TILE_B, Bhi, bn, 0, tid);
        load_tile32(st + 3 * TILE_B, Blo, bn, 0, tid);
        CP_COMMIT();
    }

    for (int c = 0; c < NCHUNKS; c++) {
        if (c + 1 < NCHUNKS) {
            uint32_t st = sb + ((c + 1) & 1) * STAGE_B;
            int k0 = (c + 1) * MBK;
            load_tile32(st + 0 * TILE_B, Ahi, bm, k0, tid);
            load_tile32(st + 1 * TILE_B, Alo, bm, k0, tid);
            load_tile32(st + 2 * TILE_B, Bhi, bn, k0, tid);
            load_tile32(st + 3 * TILE_B, Blo, bn, k0, tid);
            CP_COMMIT();
            CP_WAIT1();
        } else {
            CP_WAIT0();
        }
        __syncthreads();

        const uint32_t st = sb + (c & 1) * STAGE_B;
        const uint32_t sAhi = st + 0 * TILE_B;
        const uint32_t sAlo = st + 1 * TILE_B;
        const uint32_t sBhi = st + 2 * TILE_B;
        const uint32_t sBlo = st + 3 * TILE_B;

#pragma unroll
        for (int ks = 0; ks < 2; ks++) {
            const int kc = ks * 16;
            uint32_t ah[2][4], al[2][4], bh[8][2], bl[8][2];
#pragma unroll
            for (int ma = 0; ma < 2; ma++) {
                uint32_t off =
                    (uint32_t)((wm * 32 + ma * 16 + a_r) * (STR * 2) +
                               (kc + a_c) * 2);
                ldsm_x4(ah[ma][0], ah[ma][1], ah[ma][2], ah[ma][3], sAhi + off);
                ldsm_x4(al[ma][0], al[ma][1], al[ma][2], al[ma][3], sAlo + off);
            }
#pragma unroll
            for (int pa = 0; pa < 4; pa++) {
                uint32_t off =
                    (uint32_t)((wn * 64 + pa * 16 + b_r) * (STR * 2) +
                               (kc + b_c) * 2);
                ldsm_x4(bh[2 * pa][0], bh[2 * pa][1],
                        bh[2 * pa + 1][0], bh[2 * pa + 1][1], sBhi + off);
                ldsm_x4(bl[2 * pa][0], bl[2 * pa][1],
                        bl[2 * pa + 1][0], bl[2 * pa + 1][1], sBlo + off);
            }
#pragma unroll
            for (int ma = 0; ma < 2; ma++)
#pragma unroll
                for (int na = 0; na < 8; na++) {
                    mma_bf16(acc[ma][na], ah[ma], bh[na]);
                    mma_bf16(acc[ma][na], ah[ma], bl[na]);
                    mma_bf16(acc[ma][na], al[ma], bh[na]);
                }
        }
        __syncthreads();
    }

    // Epilogue
    const int lr = lane >> 2;        // 0..7
    const int lc = (lane & 3) * 2;   // 0,2,4,6
#pragma unroll
    for (int ma = 0; ma < 2; ma++) {
#pragma unroll
        for (int half = 0; half < 2; half++) {
            int row = bm + wm * 32 + ma * 16 + half * 8 + lr;
            int b = row / PT;
            int t = row - b * PT;
#pragma unroll
            for (int na = 0; na < 8; na++) {
                int col = bn + wn * 64 + na * 8 + lc;
                float v0 = acc[ma][na][half * 2 + 0] + bias[col + 0];
                float v1 = acc[ma][na][half * 2 + 1] + bias[col + 1];
                if (MODE == 0) {
                    float2* dst = (float2*)(C + (size_t)row * GEMM_N + col);
                    *dst = make_float2(v0, v1);
                } else {
                    int h = col >> 6;
                    int dk = col & 63;
                    float2* dst = (float2*)(C +
                        (((size_t)(b * PH + h) * PT) + t) * PDK + dk);
                    *dst = make_float2(v0, v1);
                }
            }
        }
    }
}

// ---------------------------------------------------------------------------
// Flash attention (fp32, online softmax) — unchanged passing baseline
// ---------------------------------------------------------------------------
constexpr int ABR = 64, ABC = 64, APAD = 68;
constexpr int ATTN_SMEM = 3 * 64 * APAD * 4;

__global__ __launch_bounds__(128) void attn_kernel(
    const float* __restrict__ q, const float* __restrict__ k,
    const float* __restrict__ v, float* __restrict__ o)
{
    extern __shared__ float sm[];
    float* Qs = sm;
    float* Ks = sm + 64 * APAD;
    float* Vt = sm + 2 * 64 * APAD;

    const int tid = threadIdx.x;
    const int rg = tid >> 3;
    const int cg = tid & 7;
    const int t0 = blockIdx.x * ABR;
    const int h = blockIdx.y;
    const int b = blockIdx.z;

    const float* qb = q + (((size_t)(b * PH + h) * PT) + t0) * PDK;
    const float* kb = k + (size_t)(b * PH + h) * PS * PDK;
    const float* vb = v + (size_t)(b * PH + h) * PS * PDK;

    for (int idx = tid; idx < 64 * 16; idx += 128) {
        int r = idx >> 4;
        int c4 = (idx & 15) << 2;
        float4 qv = *(const float4*)(qb + r * PDK + c4);
        Qs[r * APAD + c4 + 0] = qv.x * 0.125f;
        Qs[r * APAD + c4 + 1] = qv.y * 0.125f;
        Qs[r * APAD + c4 + 2] = qv.z * 0.125f;
        Qs[r * APAD + c4 + 3] = qv.w * 0.125f;
    }

    float m[4], l[4], O[4][8];
#pragma unroll
    for (int i = 0; i < 4; i++) {
        m[i] = -1e30f;
        l[i] = 0.f;
#pragma unroll
        for (int j = 0; j < 8; j++) O[i][j] = 0.f;
    }

    for (int s0 = 0; s0 < PS; s0 += ABC) {
        for (int idx = tid; idx < 64 * 16; idx += 128) {
            int r = idx >> 4;
            int c4 = (idx & 15) << 2;
            *(float4*)&Ks[r * APAD + c4] =
                *(const float4*)(kb + (size_t)(s0 + r) * PDK + c4);
            float4 vv = *(const float4*)(vb + (size_t)(s0 + r) * PDK + c4);
            Vt[(c4 + 0) * APAD + r] = vv.x;
            Vt[(c4 + 1) * APAD + r] = vv.y;
            Vt[(c4 + 2) * APAD + r] = vv.z;
            Vt[(c4 + 3) * APAD + r] = vv.w;
        }
        __syncthreads();

        float sc[4][8];
#pragma unroll
        for (int i = 0; i < 4; i++)
#pragma unroll
            for (int j = 0; j < 8; j++) sc[i][j] = 0.f;

#pragma unroll
        for (int kk = 0; kk < 64; kk += 4) {
            float4 qv[4], kv[8];
#pragma unroll
            for (int i = 0; i < 4; i++)
                qv[i] = *(float4*)&Qs[(rg * 4 + i) * APAD + kk];
#pragma unroll
            for (int j = 0; j < 8; j++)
                kv[j] = *(float4*)&Ks[(cg + 8 * j) * APAD + kk];
#pragma unroll
            for (int i = 0; i < 4; i++)
#pragma unroll
                for (int j = 0; j < 8; j++) {
                    sc[i][j] += qv[i].x * kv[j].x;
                    sc[i][j] += qv[i].y * kv[j].y;
                    sc[i][j] += qv[i].z * kv[j].z;
                    sc[i][j] += qv[i].w * kv[j].w;
                }
        }
        __syncthreads();

        float* Ps = Ks;
#pragma unroll
        for (int i = 0; i < 4; i++) {
            float mx = sc[i][0];
#pragma unroll
            for (int j = 1; j < 8; j++) mx = fmaxf(mx, sc[i][j]);
            mx = fmaxf(mx, __shfl_xor_sync(0xFFFFFFFFu, mx, 1));
            mx = fmaxf(mx, __shfl_xor_sync(0xFFFFFFFFu, mx, 2));
            mx = fmaxf(mx, __shfl_xor_sync(0xFFFFFFFFu, mx, 4));
            float mn = fmaxf(m[i], mx);
            float corr = __expf(m[i] - mn);
            float rs = 0.f;
#pragma unroll
            for (int j = 0; j < 8; j++) {
                float p = __expf(sc[i][j] - mn);
                sc[i][j] = p;
                rs += p;
            }
            rs += __shfl_xor_sync(0xFFFFFFFFu, rs, 1);
            rs += __shfl_xor_sync(0xFFFFFFFFu, rs, 2);
            rs += __shfl_xor_sync(0xFFFFFFFFu, rs, 4);
            l[i] = l[i] * corr + rs;
            m[i] = mn;
#pragma unroll
            for (int j = 0; j < 8; j++) O[i][j] *= corr;
#pragma unroll
            for (int j = 0; j < 8; j++)
                Ps[(rg * 4 + i) * APAD + cg + 8 * j] = sc[i][j];
        }
        __syncthreads();

#pragma unroll
        for (int ss = 0; ss < 64; ss += 4) {
            float4 pv[4], vv[8];
#pragma unroll
            for (int i = 0; i < 4; i++)
                pv[i] = *(float4*)&Ps[(rg * 4 + i) * APAD + ss];
#pragma unroll
            for (int j = 0; j < 8; j++)
                vv[j] = *(float4*)&Vt[(cg + 8 * j) * APAD + ss];
#pragma unroll
            for (int i = 0; i < 4; i++)
#pragma unroll
                for (int j = 0; j < 8; j++) {
                    O[i][j] += pv[i].x * vv[j].x;
                    O[i][j] += pv[i].y * vv[j].y;
                    O[i][j] += pv[i].z * vv[j].z;
                    O[i][j] += pv[i].w * vv[j].w;
                }
        }
        __syncthreads();
    }

#pragma unroll
    for (int i = 0; i < 4; i++) {
        float inv = 1.0f / l[i];
        int t = t0 + rg * 4 + i;
        size_t base = ((size_t)(b * PT + t)) * PD + h * PDK;
#pragma unroll
        for (int j = 0; j < 8; j++)
            o[base + cg + 8 * j] = O[i][j] * inv;
    }
}

// ---------------------------------------------------------------------------
extern "C" void kernel_launch(void* const* d_in, const int* in_sizes, int n_in,
                              void* d_out, int out_size)
{
    const float* query = (const float*)d_in[0];
    const float* value = (const float*)d_in[1];
    const float* key   = (const float*)d_in[2];
    const float* Wq    = (const float*)d_in[3];
    const float* bq    = (const float*)d_in[4];
    const float* Wk    = (const float*)d_in[5];
    const float* bk    = (const float*)d_in[6];
    const float* Wv    = (const float*)d_in[7];
    const float* bv    = (const float*)d_in[8];
    const float* Wo    = (const float*)d_in[9];
    const float* bo    = (const float*)d_in[10];
    float* out = (float*)d_out;

    float *gq, *gk, *gv, *ga;
    cudaGetSymbolAddress((void**)&gq, g_q);
    cudaGetSymbolAddress((void**)&gk, g_k);
    cudaGetSymbolAddress((void**)&gv, g_v);
    cudaGetSymbolAddress((void**)&ga, g_attn);
    __nv_bfloat16 *ahi, *alo, *bhi, *blo;
    cudaGetSymbolAddress((void**)&ahi, g_ahi);
    cudaGetSymbolAddress((void**)&alo, g_alo);
    cudaGetSymbolAddress((void**)&bhi, g_bhi);
    cudaGetSymbolAddress((void**)&blo, g_blo);

    cudaFuncSetAttribute(tc_gemm_kernel<0>,
                         cudaFuncAttributeMaxDynamicSharedMemorySize, GSM_TOTAL);
    cudaFuncSetAttribute(tc_gemm_kernel<1>,
                         cudaFuncAttributeMaxDynamicSharedMemorySize, GSM_TOTAL);
    cudaFuncSetAttribute(attn_kernel,
                         cudaFuncAttributeMaxDynamicSharedMemorySize, ATTN_SMEM);

    const int nA4 = GEMM_M * GEMM_K / 4;
    const dim3 splitAgrid((nA4 + 255) / 256);
    const dim3 splitWgrid(GEMM_N / 32, GEMM_K / 32);
    const dim3 wblock(32, 8);
    const dim3 ggrid(GEMM_N / 128, GEMM_M / 128);   // (8, 32)

    // Q projection
    split_a_kernel<<<splitAgrid, 256>>>(query, ahi, alo, nA4);
    split_w_kernel<<<splitWgrid, wblock>>>(Wq, bhi, blo);
    tc_gemm_kernel<1><<<ggrid, 256, GSM_TOTAL>>>(ahi, alo, bhi, blo, bq, gq);
    // K projection
    split_a_kernel<<<splitAgrid, 256>>>(key, ahi, alo, nA4);
    split_w_kernel<<<splitWgrid, wblock>>>(Wk, bhi, blo);
    tc_gemm_kernel<1><<<ggrid, 256, GSM_TOTAL>>>(ahi, alo, bhi, blo, bk, gk);
    // V projection
    split_a_kernel<<<splitAgrid, 256>>>(value, ahi, alo, nA4);
    split_w_kernel<<<splitWgrid, wblock>>>(Wv, bhi, blo);
    tc_gemm_kernel<1><<<ggrid, 256, GSM_TOTAL>>>(ahi, alo, bhi, blo, bv, gv);

    // Attention (fp32)
    attn_kernel<<<dim3(PT / ABR, PH, PB), 128, ATTN_SMEM>>>(gq, gk, gv, ga);

    // Output projection
    split_a_kernel<<<splitAgrid, 256>>>(ga, ahi, alo, nA4);
    split_w_kernel<<<splitWgrid, wblock>>>(Wo, bhi, blo);
    tc_gemm_kernel<0><<<ggrid, 256, GSM_TOTAL>>>(ahi, alo, bhi, blo, bo, out);
}

// round 5
// speedup vs baseline: 2.7339x; 2.1096x over previous
#include <cuda_runtime.h>
#include <cuda_bf16.h>
#include <math.h>
#include <stdint.h>

// Problem constants
constexpr int PB = 2;      // batch
constexpr int PT = 2048;   // query seq
constexpr int PS = 2048;   // key/value seq
constexpr int PD = 1024;   // model dim
constexpr int PH = 16;     // heads
constexpr int PDK = 64;    // head dim

constexpr int GEMM_M = PB * PT;  // 4096
constexpr int GEMM_N = PD;       // 1024
constexpr int GEMM_K = PD;       // 1024

// ---------------------------------------------------------------------------
// Scratch (device globals — no allocation allowed)
// ---------------------------------------------------------------------------
__device__ __nv_bfloat16 g_qhi[(size_t)PB * PH * PT * PDK];
__device__ __nv_bfloat16 g_qlo[(size_t)PB * PH * PT * PDK];
__device__ __nv_bfloat16 g_khi[(size_t)PB * PH * PS * PDK];
__device__ __nv_bfloat16 g_klo[(size_t)PB * PH * PS * PDK];
__device__ __nv_bfloat16 g_vhi[(size_t)PB * PH * PS * PDK];
__device__ __nv_bfloat16 g_vlo[(size_t)PB * PH * PS * PDK];

__device__ __nv_bfloat16 g_ahi[(size_t)GEMM_M * GEMM_K];
__device__ __nv_bfloat16 g_alo[(size_t)GEMM_M * GEMM_K];
__device__ __nv_bfloat16 g_bhi[(size_t)GEMM_N * GEMM_K];  // W^T, K-major
__device__ __nv_bfloat16 g_blo[(size_t)GEMM_N * GEMM_K];

// ---------------------------------------------------------------------------
// PTX helpers (base ISA only)
// ---------------------------------------------------------------------------
__device__ __forceinline__ uint32_t smem_u32(const void* p) {
    uint32_t a;
    asm("{ .reg .u64 t; cvta.to.shared.u64 t, %1; cvt.u32.u64 %0, t; }"
        : "=r"(a) : "l"(p));
    return a;
}

__device__ __forceinline__ void cp16(uint32_t saddr, const void* gaddr) {
    asm volatile("cp.async.cg.shared.global [%0], [%1], 16;"
                 :: "r"(saddr), "l"(gaddr) : "memory");
}
#define CP_COMMIT() asm volatile("cp.async.commit_group;" ::: "memory")
#define CP_WAIT1()  asm volatile("cp.async.wait_group 1;" ::: "memory")
#define CP_WAIT0()  asm volatile("cp.async.wait_group 0;" ::: "memory")

__device__ __forceinline__ void ldsm_x4(uint32_t& r0, uint32_t& r1,
                                        uint32_t& r2, uint32_t& r3,
                                        uint32_t addr) {
    asm volatile("ldmatrix.sync.aligned.m8n8.x4.shared.b16 {%0,%1,%2,%3}, [%4];"
                 : "=r"(r0), "=r"(r1), "=r"(r2), "=r"(r3) : "r"(addr));
}

__device__ __forceinline__ void ldsm_x4_t(uint32_t& r0, uint32_t& r1,
                                          uint32_t& r2, uint32_t& r3,
                                          uint32_t addr) {
    asm volatile("ldmatrix.sync.aligned.m8n8.x4.trans.shared.b16 {%0,%1,%2,%3}, [%4];"
                 : "=r"(r0), "=r"(r1), "=r"(r2), "=r"(r3) : "r"(addr));
}

__device__ __forceinline__ void mma_bf16(float* d, const uint32_t* a,
                                         const uint32_t* b) {
    asm volatile(
        "mma.sync.aligned.m16n8k16.row.col.f32.bf16.bf16.f32 "
        "{%0,%1,%2,%3}, {%4,%5,%6,%7}, {%8,%9}, {%0,%1,%2,%3};"
        : "+f"(d[0]), "+f"(d[1]), "+f"(d[2]), "+f"(d[3])
        : "r"(a[0]), "r"(a[1]), "r"(a[2]), "r"(a[3]),
          "r"(b[0]), "r"(b[1]));
}

// split (a, b) fp32 pair into packed bf16x2 hi + bf16x2 lo
__device__ __forceinline__ void split2(float a, float b,
                                       uint32_t& hi, uint32_t& lo) {
    __nv_bfloat16 ha = __float2bfloat16(a);
    __nv_bfloat16 hb = __float2bfloat16(b);
    hi = ((uint32_t)__bfloat16_as_ushort(hb) << 16) |
         (uint32_t)__bfloat16_as_ushort(ha);
    __nv_bfloat162 r = __floats2bfloat162_rn(a - __bfloat162float(ha),
                                             b - __bfloat162float(hb));
    lo = *reinterpret_cast<uint32_t*>(&r);
}

// ---------------------------------------------------------------------------
// Split kernels: fp32 -> bf16 hi/lo
// ---------------------------------------------------------------------------
__global__ __launch_bounds__(256) void split_a_kernel(
    const float* __restrict__ x, __nv_bfloat16* __restrict__ hi,
    __nv_bfloat16* __restrict__ lo, int n4)
{
    int i = blockIdx.x * blockDim.x + threadIdx.x;
    if (i >= n4) return;
    float4 v = ((const float4*)x)[i];
    uint32_t h0, l0, h1, l1;
    split2(v.x, v.y, h0, l0);
    split2(v.z, v.w, h1, l1);
    uint32_t* hp = (uint32_t*)hi;
    uint32_t* lp = (uint32_t*)lo;
    hp[2 * i + 0] = h0;
    hp[2 * i + 1] = h1;
    lp[2 * i + 0] = l0;
    lp[2 * i + 1] = l1;
}

// W[K][N] (row-major) -> B^T[N][K] bf16 hi/lo (K contiguous)
__global__ __launch_bounds__(256) void split_w_kernel(
    const float* __restrict__ W, __nv_bfloat16* __restrict__ hi,
    __nv_bfloat16* __restrict__ lo)
{
    __shared__ float t[32][33];
    int n0 = blockIdx.x * 32, k0 = blockIdx.y * 32;
    int tx = threadIdx.x, ty = threadIdx.y;   // block (32, 8)
#pragma unroll
    for (int i = 0; i < 32; i += 8)
        t[ty + i][tx] = W[(size_t)(k0 + ty + i) * GEMM_N + n0 + tx];
    __syncthreads();
#pragma unroll
    for (int i = 0; i < 32; i += 8) {
        float v = t[tx][ty + i];
        __nv_bfloat16 h = __float2bfloat16(v);
        size_t o = (size_t)(n0 + ty + i) * GEMM_K + k0 + tx;
        hi[o] = h;
        lo[o] = __float2bfloat16(v - __bfloat162float(h));
    }
}

// ---------------------------------------------------------------------------
// HMMA GEMM: 128x128 block, BK=32, 8 warps, hi/lo 3-pass.
// MODE 0: fp32 row-major + bias -> C.
// MODE 1: bf16 hi/lo split store to (B,H,seq,DK) -> Chi/Clo.
// ---------------------------------------------------------------------------
constexpr int MBK = 32;
constexpr int STR = 40;                         // padded row stride (bf16)
constexpr int TILE_B = 128 * STR * 2;           // 10240 bytes
constexpr int STAGE_B = 4 * TILE_B;
constexpr int GSM_TOTAL = 2 * STAGE_B;          // 81920
constexpr int NCHUNKS = GEMM_K / MBK;           // 32

__device__ __forceinline__ void load_tile32(
    uint32_t sdst, const __nv_bfloat16* __restrict__ g, int row0, int k0, int tid)
{
#pragma unroll
    for (int i = 0; i < 2; i++) {
        int s = tid + i * 256;
        int r = s >> 2;
        int c = s & 3;
        cp16(sdst + (uint32_t)(r * (STR * 2) + c * 16),
             g + (size_t)(row0 + r) * GEMM_K + k0 + c * 8);
    }
}

template <int MODE>
__global__ __launch_bounds__(256, 1) void tc_gemm_kernel(
    const __nv_bfloat16* __restrict__ Ahi, const __nv_bfloat16* __restrict__ Alo,
    const __nv_bfloat16* __restrict__ Bhi, const __nv_bfloat16* __restrict__ Blo,
    const float* __restrict__ bias, float* __restrict__ C,
    __nv_bfloat16* __restrict__ Chi, __nv_bfloat16* __restrict__ Clo)
{
    extern __shared__ __align__(128) char smem[];
    const uint32_t sb = smem_u32(smem);
    const int tid = threadIdx.x;
    const int wid = tid >> 5;
    const int lane = tid & 31;
    const int wm = wid >> 1;
    const int wn = wid & 1;
    const int bm = blockIdx.y * 128;
    const int bn = blockIdx.x * 128;

    float acc[2][8][4];
#pragma unroll
    for (int i = 0; i < 2; i++)
#pragma unroll
        for (int j = 0; j < 8; j++)
#pragma unroll
            for (int r = 0; r < 4; r++) acc[i][j][r] = 0.f;

    const int a_r = ((lane >> 3) & 1) * 8 + (lane & 7);
    const int a_c = (lane >> 4) * 8;
    const int b_r = (lane >> 4) * 8 + (lane & 7);
    const int b_c = ((lane >> 3) & 1) * 8;

    {
        uint32_t st = sb;
        load_tile32(st + 0 * TILE_B, Ahi, bm, 0, tid);
        load_tile32(st + 1 * TILE_B, Alo, bm, 0, tid);
        load_tile32(st + 2 * TILE_B, Bhi, bn, 0, tid);
        load_tile32(st + 3 * TILE_B, Blo, bn, 0, tid);
        CP_COMMIT();
    }

    for (int c = 0; c < NCHUNKS; c++) {
        if (c + 1 < NCHUNKS) {
            uint32_t st = sb + ((c + 1) & 1) * STAGE_B;
            int k0 = (c + 1) * MBK;
            load_tile32(st + 0 * TILE_B, Ahi, bm, k0, tid);
            load_tile32(st + 1 * TILE_B, Alo, bm, k0, tid);
            load_tile32(st + 2 * TILE_B, Bhi, bn, k0, tid);
            load_tile32(st + 3 * TILE_B, Blo, bn, k0, tid);
            CP_COMMIT();
            CP_WAIT1();
        } else {
            CP_WAIT0();
        }
        __syncthreads();

        const uint32_t st = sb + (c & 1) * STAGE_B;
        const uint32_t sAhi = st + 0 * TILE_B;
        const uint32_t sAlo = st + 1 * TILE_B;
        const uint32_t sBhi = st + 2 * TILE_B;
        const uint32_t sBlo = st + 3 * TILE_B;

#pragma unroll
        for (int ks = 0; ks < 2; ks++) {
            const int kc = ks * 16;
            uint32_t ah[2][4], al[2][4], bh[8][2], bl[8][2];
#pragma unroll
            for (int ma = 0; ma < 2; ma++) {
                uint32_t off =
                    (uint32_t)((wm * 32 + ma * 16 + a_r) * (STR * 2) +
                               (kc + a_c) * 2);
                ldsm_x4(ah[ma][0], ah[ma][1], ah[ma][2], ah[ma][3], sAhi + off);
                ldsm_x4(al[ma][0], al[ma][1], al[ma][2], al[ma][3], sAlo + off);
            }
#pragma unroll
            for (int pa = 0; pa < 4; pa++) {
                uint32_t off =
                    (uint32_t)((wn * 64 + pa * 16 + b_r) * (STR * 2) +
                               (kc + b_c) * 2);
                ldsm_x4(bh[2 * pa][0], bh[2 * pa][1],
                        bh[2 * pa + 1][0], bh[2 * pa + 1][1], sBhi + off);
                ldsm_x4(bl[2 * pa][0], bl[2 * pa][1],
                        bl[2 * pa + 1][0], bl[2 * pa + 1][1], sBlo + off);
            }
#pragma unroll
            for (int ma = 0; ma < 2; ma++)
#pragma unroll
                for (int na = 0; na < 8; na++) {
                    mma_bf16(acc[ma][na], ah[ma], bh[na]);
                    mma_bf16(acc[ma][na], ah[ma], bl[na]);
                    mma_bf16(acc[ma][na], al[ma], bh[na]);
                }
        }
        __syncthreads();
    }

    const int lr = lane >> 2;
    const int lc = (lane & 3) * 2;
#pragma unroll
    for (int ma = 0; ma < 2; ma++) {
#pragma unroll
        for (int half = 0; half < 2; half++) {
            int row = bm + wm * 32 + ma * 16 + half * 8 + lr;
            int b = row / PT;
            int t = row - b * PT;
#pragma unroll
            for (int na = 0; na < 8; na++) {
                int col = bn + wn * 64 + na * 8 + lc;
                float v0 = acc[ma][na][half * 2 + 0] + bias[col + 0];
                float v1 = acc[ma][na][half * 2 + 1] + bias[col + 1];
                if (MODE == 0) {
                    float2* dst = (float2*)(C + (size_t)row * GEMM_N + col);
                    *dst = make_float2(v0, v1);
                } else {
                    int h = col >> 6;
                    int dk = col & 63;
                    size_t o = (((size_t)(b * PH + h) * PT) + t) * PDK + dk;
                    uint32_t hp, lp;
                    split2(v0, v1, hp, lp);
                    *(uint32_t*)(Chi + o) = hp;
                    *(uint32_t*)(Clo + o) = lp;
                }
            }
        }
    }
}

// ---------------------------------------------------------------------------
// Flash attention on mma.sync, full hi/lo (Q,K,P,V all split).
// CTA: 128 Q rows, 4 warps (32 rows each). K/V tiles of 64, double buffered.
// ---------------------------------------------------------------------------
constexpr int ASTR = 72;                       // smem row stride in bf16
constexpr int QTILE_B = 128 * ASTR * 2;        // 18432
constexpr int KTILE_B = 64 * ASTR * 2;         // 9216
constexpr int AT_SMEM = 2 * QTILE_B + 2 * 4 * KTILE_B;  // 110592

__device__ __forceinline__ void at_load_kv(
    uint32_t base, const __nv_bfloat16* kh, const __nv_bfloat16* kl,
    const __nv_bfloat16* vh, const __nv_bfloat16* vl,
    size_t gbase, int tid)
{
#pragma unroll
    for (int i = 0; i < 4; i++) {
        int s = tid + i * 128;        // 0..511
        int r = s >> 3;
        int c = s & 7;
        uint32_t doff = (uint32_t)(r * (ASTR * 2) + c * 16);
        size_t goff = gbase + (size_t)r * PDK + c * 8;
        cp16(base + 0 * KTILE_B + doff, kh + goff);
        cp16(base + 1 * KTILE_B + doff, kl + goff);
        cp16(base + 2 * KTILE_B + doff, vh + goff);
        cp16(base + 3 * KTILE_B + doff, vl + goff);
    }
}

__global__ __launch_bounds__(128, 1) void attn_mma_kernel(
    const __nv_bfloat16* __restrict__ qhi, const __nv_bfloat16* __restrict__ qlo,
    const __nv_bfloat16* __restrict__ khi, const __nv_bfloat16* __restrict__ klo,
    const __nv_bfloat16* __restrict__ vhi, const __nv_bfloat16* __restrict__ vlo,
    __nv_bfloat16* __restrict__ ohi, __nv_bfloat16* __restrict__ olo)
{
    extern __shared__ __align__(128) char smem[];
    const uint32_t sb = smem_u32(smem);
    const int tid = threadIdx.x;
    const int w = tid >> 5;
    const int lane = tid & 31;
    const int t0 = blockIdx.x * 128;
    const int h = blockIdx.y;
    const int b = blockIdx.z;
    const size_t bh = (size_t)(b * PH + h);

    const int a_r = ((lane >> 3) & 1) * 8 + (lane & 7);
    const int a_c = (lane >> 4) * 8;
    const int b_r = (lane >> 4) * 8 + (lane & 7);
    const int b_c = ((lane >> 3) & 1) * 8;

    // Load Q tiles (hi/lo) + first K/V tile, one commit group
    {
        const __nv_bfloat16* qhb = qhi + (bh * PT + t0) * PDK;
        const __nv_bfloat16* qlb = qlo + (bh * PT + t0) * PDK;
#pragma unroll
        for (int i = 0; i < 8; i++) {
            int s = tid + i * 128;        // 0..1023
            int r = s >> 3;
            int c = s & 7;
            uint32_t doff = (uint32_t)(r * (ASTR * 2) + c * 16);
            cp16(sb + doff, qhb + (size_t)r * PDK + c * 8);
            cp16(sb + QTILE_B + doff, qlb + (size_t)r * PDK + c * 8);
        }
        at_load_kv(sb + 2 * QTILE_B, khi, klo, vhi, vlo, bh * PS * PDK, tid);
        CP_COMMIT();
    }

    float m[2][2], l[2][2];
    float oa[2][8][4];
#pragma unroll
    for (int i = 0; i < 2; i++)
#pragma unroll
        for (int j = 0; j < 2; j++) { m[i][j] = -1e30f; l[i][j] = 0.f; }
#pragma unroll
    for (int i = 0; i < 2; i++)
#pragma unroll
        for (int j = 0; j < 8; j++)
#pragma unroll
            for (int r = 0; r < 4; r++) oa[i][j][r] = 0.f;

    const int NT = PS / 64;   // 32 tiles

    for (int it = 0; it < NT; it++) {
        const int stage = it & 1;
        if (it + 1 < NT) {
            at_load_kv(sb + 2 * QTILE_B + (stage ^ 1) * 4 * KTILE_B,
                       khi, klo, vhi, vlo,
                       (bh * PS + (size_t)(it + 1) * 64) * PDK, tid);
            CP_COMMIT();
            CP_WAIT1();
        } else {
            CP_WAIT0();
        }
        __syncthreads();

        const uint32_t kb = sb + 2 * QTILE_B + stage * 4 * KTILE_B;
        const uint32_t sKh = kb + 0 * KTILE_B;
        const uint32_t sKl = kb + 1 * KTILE_B;
        const uint32_t sVh = kb + 2 * KTILE_B;
        const uint32_t sVl = kb + 3 * KTILE_B;

        // ---- S = Q K^T (3-pass hi/lo) ----
        float sc[2][8][4];
#pragma unroll
        for (int i = 0; i < 2; i++)
#pragma unroll
            for (int j = 0; j < 8; j++)
#pragma unroll
                for (int r = 0; r < 4; r++) sc[i][j][r] = 0.f;

#pragma unroll
        for (int kk = 0; kk < 4; kk++) {
            const int kc = kk * 16;
            uint32_t qh[2][4], ql[2][4], kh[8][2], kl[8][2];
#pragma unroll
            for (int ma = 0; ma < 2; ma++) {
                uint32_t off = (uint32_t)((w * 32 + ma * 16 + a_r) * (ASTR * 2) +
                                          (kc + a_c) * 2);
                ldsm_x4(qh[ma][0], qh[ma][1], qh[ma][2], qh[ma][3], sb + off);
                ldsm_x4(ql[ma][0], ql[ma][1], ql[ma][2], ql[ma][3],
                        sb + QTILE_B + off);
            }
#pragma unroll
            for (int nb = 0; nb < 4; nb++) {
                uint32_t off = (uint32_t)((nb * 16 + b_r) * (ASTR * 2) +
                                          (kc + b_c) * 2);
                ldsm_x4(kh[2 * nb][0], kh[2 * nb][1],
                        kh[2 * nb + 1][0], kh[2 * nb + 1][1], sKh + off);
                ldsm_x4(kl[2 * nb][0], kl[2 * nb][1],
                        kl[2 * nb + 1][0], kl[2 * nb + 1][1], sKl + off);
            }
#pragma unroll
            for (int ma = 0; ma < 2; ma++)
#pragma unroll
                for (int na = 0; na < 8; na++) {
                    mma_bf16(sc[ma][na], qh[ma], kh[na]);
                    mma_bf16(sc[ma][na], qh[ma], kl[na]);
                    mma_bf16(sc[ma][na], ql[ma], kh[na]);
                }
        }

        // ---- online softmax (scale 1/sqrt(64) = 0.125) ----
#pragma unroll
        for (int ma = 0; ma < 2; ma++) {
            float mx0 = -1e30f, mx1 = -1e30f;
#pragma unroll
            for (int na = 0; na < 8; na++) {
#pragma unroll
                for (int r = 0; r < 4; r++) sc[ma][na][r] *= 0.125f;
                mx0 = fmaxf(mx0, fmaxf(sc[ma][na][0], sc[ma][na][1]));
                mx1 = fmaxf(mx1, fmaxf(sc[ma][na][2], sc[ma][na][3]));
            }
            mx0 = fmaxf(mx0, __shfl_xor_sync(0xFFFFFFFFu, mx0, 1));
            mx0 = fmaxf(mx0, __shfl_xor_sync(0xFFFFFFFFu, mx0, 2));
            mx1 = fmaxf(mx1, __shfl_xor_sync(0xFFFFFFFFu, mx1, 1));
            mx1 = fmaxf(mx1, __shfl_xor_sync(0xFFFFFFFFu, mx1, 2));
            float mn0 = fmaxf(m[ma][0], mx0);
            float mn1 = fmaxf(m[ma][1], mx1);
            float c0 = __expf(m[ma][0] - mn0);
            float c1 = __expf(m[ma][1] - mn1);
            float rs0 = 0.f, rs1 = 0.f;
#pragma unroll
            for (int na = 0; na < 8; na++) {
                float p0 = __expf(sc[ma][na][0] - mn0);
                float p1 = __expf(sc[ma][na][1] - mn0);
                float p2 = __expf(sc[ma][na][2] - mn1);
                float p3 = __expf(sc[ma][na][3] - mn1);
                sc[ma][na][0] = p0; sc[ma][na][1] = p1;
                sc[ma][na][2] = p2; sc[ma][na][3] = p3;
                rs0 += p0 + p1;
                rs1 += p2 + p3;
            }
            rs0 += __shfl_xor_sync(0xFFFFFFFFu, rs0, 1);
            rs0 += __shfl_xor_sync(0xFFFFFFFFu, rs0, 2);
            rs1 += __shfl_xor_sync(0xFFFFFFFFu, rs1, 1);
            rs1 += __shfl_xor_sync(0xFFFFFFFFu, rs1, 2);
            l[ma][0] = l[ma][0] * c0 + rs0;
            l[ma][1] = l[ma][1] * c1 + rs1;
            m[ma][0] = mn0;
            m[ma][1] = mn1;
#pragma unroll
            for (int nb = 0; nb < 8; nb++) {
                oa[ma][nb][0] *= c0;
                oa[ma][nb][1] *= c0;
                oa[ma][nb][2] *= c1;
                oa[ma][nb][3] *= c1;
            }
        }

        // ---- O += P V (3-pass hi/lo; P from registers, V via ldmatrix.trans) ----
#pragma unroll
        for (int kk = 0; kk < 4; kk++) {
            uint32_t ph[2][4], pl[2][4];
#pragma unroll
            for (int ma = 0; ma < 2; ma++) {
                split2(sc[ma][2 * kk][0],     sc[ma][2 * kk][1],     ph[ma][0], pl[ma][0]);
                split2(sc[ma][2 * kk][2],     sc[ma][2 * kk][3],     ph[ma][1], pl[ma][1]);
                split2(sc[ma][2 * kk + 1][0], sc[ma][2 * kk + 1][1], ph[ma][2], pl[ma][2]);
                split2(sc[ma][2 * kk + 1][2], sc[ma][2 * kk + 1][3], ph[ma][3], pl[ma][3]);
            }
            uint32_t vh[8][2], vl[8][2];
#pragma unroll
            for (int db = 0; db < 4; db++) {
                uint32_t off = (uint32_t)((kk * 16 + a_r) * (ASTR * 2) +
                                          (db * 16 + a_c) * 2);
                ldsm_x4_t(vh[2 * db][0], vh[2 * db][1],
                          vh[2 * db + 1][0], vh[2 * db + 1][1], sVh + off);
                ldsm_x4_t(vl[2 * db][0], vl[2 * db][1],
                          vl[2 * db + 1][0], vl[2 * db + 1][1], sVl + off);
            }
#pragma unroll
            for (int ma = 0; ma < 2; ma++)
#pragma unroll
                for (int nb = 0; nb < 8; nb++) {
                    mma_bf16(oa[ma][nb], ph[ma], vh[nb]);
                    mma_bf16(oa[ma][nb], ph[ma], vl[nb]);
                    mma_bf16(oa[ma][nb], pl[ma], vh[nb]);
                }
        }
        __syncthreads();
    }

    // ---- epilogue: O/l, split hi/lo, write (B,T,H*DK) ----
#pragma unroll
    for (int ma = 0; ma < 2; ma++) {
#pragma unroll
        for (int half = 0; half < 2; half++) {
            int t = t0 + w * 32 + ma * 16 + half * 8 + (lane >> 2);
            float invl = 1.0f / l[ma][half];
            size_t base = ((size_t)(b * PT + t)) * PD + h * PDK;
#pragma unroll
            for (int nb = 0; nb < 8; nb++) {
                int col = nb * 8 + 2 * (lane & 3);
                float v0 = oa[ma][nb][half * 2 + 0] * invl;
                float v1 = oa[ma][nb][half * 2 + 1] * invl;
                uint32_t hp, lp;
                split2(v0, v1, hp, lp);
                *(uint32_t*)(ohi + base + col) = hp;
                *(uint32_t*)(olo + base + col) = lp;
            }
        }
    }
}

// ---------------------------------------------------------------------------
extern "C" void kernel_launch(void* const* d_in, const int* in_sizes, int n_in,
                              void* d_out, int out_size)
{
    const float* query = (const float*)d_in[0];
    const float* value = (const float*)d_in[1];
    const float* key   = (const float*)d_in[2];
    const float* Wq    = (const float*)d_in[3];
    const float* bq    = (const float*)d_in[4];
    const float* Wk    = (const float*)d_in[5];
    const float* bk    = (const float*)d_in[6];
    const float* Wv    = (const float*)d_in[7];
    const float* bv    = (const float*)d_in[8];
    const float* Wo    = (const float*)d_in[9];
    const float* bo    = (const float*)d_in[10];
    float* out = (float*)d_out;

    __nv_bfloat16 *qhi, *qlo, *khi, *klo, *vhi, *vlo, *ahi, *alo, *bhi, *blo;
    cudaGetSymbolAddress((void**)&qhi, g_qhi);
    cudaGetSymbolAddress((void**)&qlo, g_qlo);
    cudaGetSymbolAddress((void**)&khi, g_khi);
    cudaGetSymbolAddress((void**)&klo, g_klo);
    cudaGetSymbolAddress((void**)&vhi, g_vhi);
    cudaGetSymbolAddress((void**)&vlo, g_vlo);
    cudaGetSymbolAddress((void**)&ahi, g_ahi);
    cudaGetSymbolAddress((void**)&alo, g_alo);
    cudaGetSymbolAddress((void**)&bhi, g_bhi);
    cudaGetSymbolAddress((void**)&blo, g_blo);

    cudaFuncSetAttribute(tc_gemm_kernel<0>,
                         cudaFuncAttributeMaxDynamicSharedMemorySize, GSM_TOTAL);
    cudaFuncSetAttribute(tc_gemm_kernel<1>,
                         cudaFuncAttributeMaxDynamicSharedMemorySize, GSM_TOTAL);
    cudaFuncSetAttribute(attn_mma_kernel,
                         cudaFuncAttributeMaxDynamicSharedMemorySize, AT_SMEM);

    const int nA4 = GEMM_M * GEMM_K / 4;
    const dim3 splitAgrid((nA4 + 255) / 256);
    const dim3 splitWgrid(GEMM_N / 32, GEMM_K / 32);
    const dim3 wblock(32, 8);
    const dim3 ggrid(GEMM_N / 128, GEMM_M / 128);

    // Q projection -> bf16 hi/lo (B,H,T,DK)
    split_a_kernel<<<splitAgrid, 256>>>(query, ahi, alo, nA4);
    split_w_kernel<<<splitWgrid, wblock>>>(Wq, bhi, blo);
    tc_gemm_kernel<1><<<ggrid, 256, GSM_TOTAL>>>(ahi, alo, bhi, blo, bq,
                                                 nullptr, qhi, qlo);
    // K projection
    split_a_kernel<<<splitAgrid, 256>>>(key, ahi, alo, nA4);
    split_w_kernel<<<splitWgrid, wblock>>>(Wk, bhi, blo);
    tc_gemm_kernel<1><<<ggrid, 256, GSM_TOTAL>>>(ahi, alo, bhi, blo, bk,
                                                 nullptr, khi, klo);
    // V projection
    split_a_kernel<<<splitAgrid, 256>>>(value, ahi, alo, nA4);
    split_w_kernel<<<splitWgrid, wblock>>>(Wv, bhi, blo);
    tc_gemm_kernel<1><<<ggrid, 256, GSM_TOTAL>>>(ahi, alo, bhi, blo, bv,
                                                 nullptr, vhi, vlo);

    // Attention (tensor cores, hi/lo) -> writes ahi/alo (B,T,D)
    attn_mma_kernel<<<dim3(PT / 128, PH, PB), 128, AT_SMEM>>>(
        qhi, qlo, khi, klo, vhi, vlo, ahi, alo);

    // Output projection (fp32 out)
    split_w_kernel<<<splitWgrid, wblock>>>(Wo, bhi, blo);
    tc_gemm_kernel<0><<<ggrid, 256, GSM_TOTAL>>>(ahi, alo, bhi, blo, bo,
                                                 out, nullptr, nullptr);
}

// round 6
// speedup vs baseline: 2.8533x; 1.0437x over previous
#include <cuda_runtime.h>
#include <cuda_bf16.h>
#include <math.h>
#include <stdint.h>

// Problem constants
constexpr int PB = 2;      // batch
constexpr int PT = 2048;   // query seq
constexpr int PS = 2048;   // key/value seq
constexpr int PD = 1024;   // model dim
constexpr int PH = 16;     // heads
constexpr int PDK = 64;    // head dim

constexpr int GEMM_M = PB * PT;  // 4096
constexpr int GEMM_N = PD;       // 1024
constexpr int GEMM_K = PD;       // 1024

// ---------------------------------------------------------------------------
// Scratch (device globals — no allocation allowed)
// ---------------------------------------------------------------------------
__device__ __nv_bfloat16 g_qhi[(size_t)PB * PH * PT * PDK];
__device__ __nv_bfloat16 g_qlo[(size_t)PB * PH * PT * PDK];
__device__ __nv_bfloat16 g_khi[(size_t)PB * PH * PS * PDK];
__device__ __nv_bfloat16 g_klo[(size_t)PB * PH * PS * PDK];
__device__ __nv_bfloat16 g_vhi[(size_t)PB * PH * PS * PDK];
__device__ __nv_bfloat16 g_vlo[(size_t)PB * PH * PS * PDK];

// projection inputs split (query, key, value)
__device__ __nv_bfloat16 g_pa_hi[3][(size_t)GEMM_M * GEMM_K];
__device__ __nv_bfloat16 g_pa_lo[3][(size_t)GEMM_M * GEMM_K];
// weights transposed split (Wq, Wk, Wv, Wo), [N][K] K-major
__device__ __nv_bfloat16 g_pb_hi[4][(size_t)GEMM_N * GEMM_K];
__device__ __nv_bfloat16 g_pb_lo[4][(size_t)GEMM_N * GEMM_K];
// attention output split (A of output GEMM)
__device__ __nv_bfloat16 g_ahi[(size_t)GEMM_M * GEMM_K];
__device__ __nv_bfloat16 g_alo[(size_t)GEMM_M * GEMM_K];

// ---------------------------------------------------------------------------
// PTX helpers (base ISA only)
// ---------------------------------------------------------------------------
__device__ __forceinline__ uint32_t smem_u32(const void* p) {
    uint32_t a;
    asm("{ .reg .u64 t; cvta.to.shared.u64 t, %1; cvt.u32.u64 %0, t; }"
        : "=r"(a) : "l"(p));
    return a;
}

__device__ __forceinline__ void cp16(uint32_t saddr, const void* gaddr) {
    asm volatile("cp.async.cg.shared.global [%0], [%1], 16;"
                 :: "r"(saddr), "l"(gaddr) : "memory");
}
#define CP_COMMIT() asm volatile("cp.async.commit_group;" ::: "memory")
#define CP_WAIT1()  asm volatile("cp.async.wait_group 1;" ::: "memory")
#define CP_WAIT0()  asm volatile("cp.async.wait_group 0;" ::: "memory")

__device__ __forceinline__ void ldsm_x4(uint32_t& r0, uint32_t& r1,
                                        uint32_t& r2, uint32_t& r3,
                                        uint32_t addr) {
    asm volatile("ldmatrix.sync.aligned.m8n8.x4.shared.b16 {%0,%1,%2,%3}, [%4];"
                 : "=r"(r0), "=r"(r1), "=r"(r2), "=r"(r3) : "r"(addr));
}

__device__ __forceinline__ void ldsm_x4_t(uint32_t& r0, uint32_t& r1,
                                          uint32_t& r2, uint32_t& r3,
                                          uint32_t addr) {
    asm volatile("ldmatrix.sync.aligned.m8n8.x4.trans.shared.b16 {%0,%1,%2,%3}, [%4];"
                 : "=r"(r0), "=r"(r1), "=r"(r2), "=r"(r3) : "r"(addr));
}

__device__ __forceinline__ void mma_bf16(float* d, const uint32_t* a,
                                         const uint32_t* b) {
    asm volatile(
        "mma.sync.aligned.m16n8k16.row.col.f32.bf16.bf16.f32 "
        "{%0,%1,%2,%3}, {%4,%5,%6,%7}, {%8,%9}, {%0,%1,%2,%3};"
        : "+f"(d[0]), "+f"(d[1]), "+f"(d[2]), "+f"(d[3])
        : "r"(a[0]), "r"(a[1]), "r"(a[2]), "r"(a[3]),
          "r"(b[0]), "r"(b[1]));
}

// split (a, b) fp32 pair into packed bf16x2 hi + bf16x2 lo
__device__ __forceinline__ void split2(float a, float b,
                                       uint32_t& hi, uint32_t& lo) {
    __nv_bfloat16 ha = __float2bfloat16(a);
    __nv_bfloat16 hb = __float2bfloat16(b);
    hi = ((uint32_t)__bfloat16_as_ushort(hb) << 16) |
         (uint32_t)__bfloat16_as_ushort(ha);
    __nv_bfloat162 r = __floats2bfloat162_rn(a - __bfloat162float(ha),
                                             b - __bfloat162float(hb));
    lo = *reinterpret_cast<uint32_t*>(&r);
}

// ---------------------------------------------------------------------------
// Split kernels (fused over z planes)
// ---------------------------------------------------------------------------
struct SplitAParams {
    const float* x[3];
    __nv_bfloat16* hi[3];
    __nv_bfloat16* lo[3];
};

__global__ __launch_bounds__(256) void split_a3_kernel(SplitAParams P, int n4)
{
    int z = blockIdx.z;
    int i = blockIdx.x * blockDim.x + threadIdx.x;
    if (i >= n4) return;
    float4 v = ((const float4*)P.x[z])[i];
    uint32_t h0, l0, h1, l1;
    split2(v.x, v.y, h0, l0);
    split2(v.z, v.w, h1, l1);
    uint32_t* hp = (uint32_t*)P.hi[z];
    uint32_t* lp = (uint32_t*)P.lo[z];
    hp[2 * i + 0] = h0;
    hp[2 * i + 1] = h1;
    lp[2 * i + 0] = l0;
    lp[2 * i + 1] = l1;
}

struct SplitWParams {
    const float* w[4];
    __nv_bfloat16* hi[4];
    __nv_bfloat16* lo[4];
};

// W[K][N] (row-major) -> W^T[N][K] bf16 hi/lo (K contiguous)
__global__ __launch_bounds__(256) void split_w4_kernel(SplitWParams P)
{
    __shared__ float t[32][33];
    int z = blockIdx.z;
    const float* W = P.w[z];
    __nv_bfloat16* hi = P.hi[z];
    __nv_bfloat16* lo = P.lo[z];
    int n0 = blockIdx.x * 32, k0 = blockIdx.y * 32;
    int tx = threadIdx.x, ty = threadIdx.y;   // block (32, 8)
#pragma unroll
    for (int i = 0; i < 32; i += 8)
        t[ty + i][tx] = W[(size_t)(k0 + ty + i) * GEMM_N + n0 + tx];
    __syncthreads();
#pragma unroll
    for (int i = 0; i < 32; i += 8) {
        float v = t[tx][ty + i];
        __nv_bfloat16 h = __float2bfloat16(v);
        size_t o = (size_t)(n0 + ty + i) * GEMM_K + k0 + tx;
        hi[o] = h;
        lo[o] = __float2bfloat16(v - __bfloat162float(h));
    }
}

// ---------------------------------------------------------------------------
// HMMA GEMM core: 128x128 block, BK=64 (4 k16 steps per sync), 8 warps,
// hi/lo 3-pass. Smem row stride 72 bf16 (attention-proven layout).
// ---------------------------------------------------------------------------
constexpr int GBK = 64;
constexpr int GSTR = 72;                        // bf16 row stride
constexpr int GTILE_B = 128 * GSTR * 2;         // 18432
constexpr int GSTAGE_B = 4 * GTILE_B;           // 73728
constexpr int GSM_TOTAL = 2 * GSTAGE_B;         // 147456
constexpr int GNCH = GEMM_K / GBK;              // 16

__device__ __forceinline__ void g_load_tile(
    uint32_t sdst, const __nv_bfloat16* __restrict__ g, int row0, int k0, int tid)
{
    // 128 rows x 64 bf16 = 8 x 16B segs/row; 1024 segs / 256 thr = 4 each
#pragma unroll
    for (int i = 0; i < 4; i++) {
        int s = tid + i * 256;
        int r = s >> 3;
        int c = s & 7;
        cp16(sdst + (uint32_t)(r * (GSTR * 2) + c * 16),
             g + (size_t)(row0 + r) * GEMM_K + k0 + c * 8);
    }
}

__device__ __forceinline__ void gemm_core(
    uint32_t sb, int tid,
    const __nv_bfloat16* __restrict__ Ahi, const __nv_bfloat16* __restrict__ Alo,
    const __nv_bfloat16* __restrict__ Bhi, const __nv_bfloat16* __restrict__ Blo,
    int bm, int bn, float acc[2][8][4])
{
    const int lane = tid & 31;
    const int wid = tid >> 5;
    const int wm = wid >> 1;
    const int wn = wid & 1;

    const int a_r = ((lane >> 3) & 1) * 8 + (lane & 7);
    const int a_c = (lane >> 4) * 8;
    const int b_r = (lane >> 4) * 8 + (lane & 7);
    const int b_c = ((lane >> 3) & 1) * 8;

    // prologue: stage 0
    g_load_tile(sb + 0 * GTILE_B, Ahi, bm, 0, tid);
    g_load_tile(sb + 1 * GTILE_B, Alo, bm, 0, tid);
    g_load_tile(sb + 2 * GTILE_B, Bhi, bn, 0, tid);
    g_load_tile(sb + 3 * GTILE_B, Blo, bn, 0, tid);
    CP_COMMIT();

    for (int c = 0; c < GNCH; c++) {
        if (c + 1 < GNCH) {
            uint32_t st = sb + ((c + 1) & 1) * GSTAGE_B;
            int k0 = (c + 1) * GBK;
            g_load_tile(st + 0 * GTILE_B, Ahi, bm, k0, tid);
            g_load_tile(st + 1 * GTILE_B, Alo, bm, k0, tid);
            g_load_tile(st + 2 * GTILE_B, Bhi, bn, k0, tid);
            g_load_tile(st + 3 * GTILE_B, Blo, bn, k0, tid);
            CP_COMMIT();
            CP_WAIT1();
        } else {
            CP_WAIT0();
        }
        __syncthreads();

        const uint32_t st = sb + (c & 1) * GSTAGE_B;
        const uint32_t sAhi = st + 0 * GTILE_B;
        const uint32_t sAlo = st + 1 * GTILE_B;
        const uint32_t sBhi = st + 2 * GTILE_B;
        const uint32_t sBlo = st + 3 * GTILE_B;

#pragma unroll
        for (int ks = 0; ks < 4; ks++) {
            const int kc = ks * 16;
            uint32_t ah[2][4], al[2][4], bh[8][2], bl[8][2];
#pragma unroll
            for (int ma = 0; ma < 2; ma++) {
                uint32_t off =
                    (uint32_t)((wm * 32 + ma * 16 + a_r) * (GSTR * 2) +
                               (kc + a_c) * 2);
                ldsm_x4(ah[ma][0], ah[ma][1], ah[ma][2], ah[ma][3], sAhi + off);
                ldsm_x4(al[ma][0], al[ma][1], al[ma][2], al[ma][3], sAlo + off);
            }
#pragma unroll
            for (int pa = 0; pa < 4; pa++) {
                uint32_t off =
                    (uint32_t)((wn * 64 + pa * 16 + b_r) * (GSTR * 2) +
                               (kc + b_c) * 2);
                ldsm_x4(bh[2 * pa][0], bh[2 * pa][1],
                        bh[2 * pa + 1][0], bh[2 * pa + 1][1], sBhi + off);
                ldsm_x4(bl[2 * pa][0], bl[2 * pa][1],
                        bl[2 * pa + 1][0], bl[2 * pa + 1][1], sBlo + off);
            }
#pragma unroll
            for (int ma = 0; ma < 2; ma++)
#pragma unroll
                for (int na = 0; na < 8; na++) {
                    mma_bf16(acc[ma][na], ah[ma], bh[na]);
                    mma_bf16(acc[ma][na], ah[ma], bl[na]);
                    mma_bf16(acc[ma][na], al[ma], bh[na]);
                }
        }
        __syncthreads();
    }
}

// Fused 3-way projection GEMM: z selects (input, W, bias, dest).
// Stores bf16 hi/lo split to (B,H,seq,DK).
struct ProjParams {
    const __nv_bfloat16* ah[3];
    const __nv_bfloat16* al[3];
    const __nv_bfloat16* bh[3];
    const __nv_bfloat16* bl[3];
    const float* bias[3];
    __nv_bfloat16* ch[3];
    __nv_bfloat16* cl[3];
};

__global__ __launch_bounds__(256, 1) void proj_gemm3_kernel(ProjParams P)
{
    extern __shared__ __align__(128) char smem[];
    const uint32_t sb = smem_u32(smem);
    const int tid = threadIdx.x;
    const int z = blockIdx.z;
    const int bm = blockIdx.y * 128;
    const int bn = blockIdx.x * 128;

    float acc[2][8][4];
#pragma unroll
    for (int i = 0; i < 2; i++)
#pragma unroll
        for (int j = 0; j < 8; j++)
#pragma unroll
            for (int r = 0; r < 4; r++) acc[i][j][r] = 0.f;

    gemm_core(sb, tid, P.ah[z], P.al[z], P.bh[z], P.bl[z], bm, bn, acc);

    const float* bias = P.bias[z];
    __nv_bfloat16* Chi = P.ch[z];
    __nv_bfloat16* Clo = P.cl[z];
    const int wid = tid >> 5;
    const int lane = tid & 31;
    const int wm = wid >> 1;
    const int wn = wid & 1;
    const int lr = lane >> 2;
    const int lc = (lane & 3) * 2;
#pragma unroll
    for (int ma = 0; ma < 2; ma++) {
#pragma unroll
        for (int half = 0; half < 2; half++) {
            int row = bm + wm * 32 + ma * 16 + half * 8 + lr;
            int b = row / PT;
            int t = row - b * PT;
#pragma unroll
            for (int na = 0; na < 8; na++) {
                int col = bn + wn * 64 + na * 8 + lc;
                float v0 = acc[ma][na][half * 2 + 0] + bias[col + 0];
                float v1 = acc[ma][na][half * 2 + 1] + bias[col + 1];
                int h = col >> 6;
                int dk = col & 63;
                size_t o = (((size_t)(b * PH + h) * PT) + t) * PDK + dk;
                uint32_t hp, lp;
                split2(v0, v1, hp, lp);
                *(uint32_t*)(Chi + o) = hp;
                *(uint32_t*)(Clo + o) = lp;
            }
        }
    }
}

// Output projection GEMM: fp32 row-major + bias.
__global__ __launch_bounds__(256, 1) void out_gemm_kernel(
    const __nv_bfloat16* __restrict__ Ahi, const __nv_bfloat16* __restrict__ Alo,
    const __nv_bfloat16* __restrict__ Bhi, const __nv_bfloat16* __restrict__ Blo,
    const float* __restrict__ bias, float* __restrict__ C)
{
    extern __shared__ __align__(128) char smem[];
    const uint32_t sb = smem_u32(smem);
    const int tid = threadIdx.x;
    const int bm = blockIdx.y * 128;
    const int bn = blockIdx.x * 128;

    float acc[2][8][4];
#pragma unroll
    for (int i = 0; i < 2; i++)
#pragma unroll
        for (int j = 0; j < 8; j++)
#pragma unroll
            for (int r = 0; r < 4; r++) acc[i][j][r] = 0.f;

    gemm_core(sb, tid, Ahi, Alo, Bhi, Blo, bm, bn, acc);

    const int wid = tid >> 5;
    const int lane = tid & 31;
    const int wm = wid >> 1;
    const int wn = wid & 1;
    const int lr = lane >> 2;
    const int lc = (lane & 3) * 2;
#pragma unroll
    for (int ma = 0; ma < 2; ma++) {
#pragma unroll
        for (int half = 0; half < 2; half++) {
            int row = bm + wm * 32 + ma * 16 + half * 8 + lr;
#pragma unroll
            for (int na = 0; na < 8; na++) {
                int col = bn + wn * 64 + na * 8 + lc;
                float v0 = acc[ma][na][half * 2 + 0] + bias[col + 0];
                float v1 = acc[ma][na][half * 2 + 1] + bias[col + 1];
                float2* dst = (float2*)(C + (size_t)row * GEMM_N + col);
                *dst = make_float2(v0, v1);
            }
        }
    }
}

// ---------------------------------------------------------------------------
// Flash attention on mma.sync, full hi/lo (unchanged from Round 5)
// ---------------------------------------------------------------------------
constexpr int ASTR = 72;                       // smem row stride in bf16
constexpr int QTILE_B = 128 * ASTR * 2;        // 18432
constexpr int KTILE_B = 64 * ASTR * 2;         // 9216
constexpr int AT_SMEM = 2 * QTILE_B + 2 * 4 * KTILE_B;  // 110592

__device__ __forceinline__ void at_load_kv(
    uint32_t base, const __nv_bfloat16* kh, const __nv_bfloat16* kl,
    const __nv_bfloat16* vh, const __nv_bfloat16* vl,
    size_t gbase, int tid)
{
#pragma unroll
    for (int i = 0; i < 4; i++) {
        int s = tid + i * 128;        // 0..511
        int r = s >> 3;
        int c = s & 7;
        uint32_t doff = (uint32_t)(r * (ASTR * 2) + c * 16);
        size_t goff = gbase + (size_t)r * PDK + c * 8;
        cp16(base + 0 * KTILE_B + doff, kh + goff);
        cp16(base + 1 * KTILE_B + doff, kl + goff);
        cp16(base + 2 * KTILE_B + doff, vh + goff);
        cp16(base + 3 * KTILE_B + doff, vl + goff);
    }
}

__global__ __launch_bounds__(128, 1) void attn_mma_kernel(
    const __nv_bfloat16* __restrict__ qhi, const __nv_bfloat16* __restrict__ qlo,
    const __nv_bfloat16* __restrict__ khi, const __nv_bfloat16* __restrict__ klo,
    const __nv_bfloat16* __restrict__ vhi, const __nv_bfloat16* __restrict__ vlo,
    __nv_bfloat16* __restrict__ ohi, __nv_bfloat16* __restrict__ olo)
{
    extern __shared__ __align__(128) char smem[];
    const uint32_t sb = smem_u32(smem);
    const int tid = threadIdx.x;
    const int w = tid >> 5;
    const int lane = tid & 31;
    const int t0 = blockIdx.x * 128;
    const int h = blockIdx.y;
    const int b = blockIdx.z;
    const size_t bh = (size_t)(b * PH + h);

    const int a_r = ((lane >> 3) & 1) * 8 + (lane & 7);
    const int a_c = (lane >> 4) * 8;
    const int b_r = (lane >> 4) * 8 + (lane & 7);
    const int b_c = ((lane >> 3) & 1) * 8;

    {
        const __nv_bfloat16* qhb = qhi + (bh * PT + t0) * PDK;
        const __nv_bfloat16* qlb = qlo + (bh * PT + t0) * PDK;
#pragma unroll
        for (int i = 0; i < 8; i++) {
            int s = tid + i * 128;
            int r = s >> 3;
            int c = s & 7;
            uint32_t doff = (uint32_t)(r * (ASTR * 2) + c * 16);
            cp16(sb + doff, qhb + (size_t)r * PDK + c * 8);
            cp16(sb + QTILE_B + doff, qlb + (size_t)r * PDK + c * 8);
        }
        at_load_kv(sb + 2 * QTILE_B, khi, klo, vhi, vlo, bh * PS * PDK, tid);
        CP_COMMIT();
    }

    float m[2][2], l[2][2];
    float oa[2][8][4];
#pragma unroll
    for (int i = 0; i < 2; i++)
#pragma unroll
        for (int j = 0; j < 2; j++) { m[i][j] = -1e30f; l[i][j] = 0.f; }
#pragma unroll
    for (int i = 0; i < 2; i++)
#pragma unroll
        for (int j = 0; j < 8; j++)
#pragma unroll
            for (int r = 0; r < 4; r++) oa[i][j][r] = 0.f;

    const int NT = PS / 64;

    for (int it = 0; it < NT; it++) {
        const int stage = it & 1;
        if (it + 1 < NT) {
            at_load_kv(sb + 2 * QTILE_B + (stage ^ 1) * 4 * KTILE_B,
                       khi, klo, vhi, vlo,
                       (bh * PS + (size_t)(it + 1) * 64) * PDK, tid);
            CP_COMMIT();
            CP_WAIT1();
        } else {
            CP_WAIT0();
        }
        __syncthreads();

        const uint32_t kb = sb + 2 * QTILE_B + stage * 4 * KTILE_B;
        const uint32_t sKh = kb + 0 * KTILE_B;
        const uint32_t sKl = kb + 1 * KTILE_B;
        const uint32_t sVh = kb + 2 * KTILE_B;
        const uint32_t sVl = kb + 3 * KTILE_B;

        float sc[2][8][4];
#pragma unroll
        for (int i = 0; i < 2; i++)
#pragma unroll
            for (int j = 0; j < 8; j++)
#pragma unroll
                for (int r = 0; r < 4; r++) sc[i][j][r] = 0.f;

#pragma unroll
        for (int kk = 0; kk < 4; kk++) {
            const int kc = kk * 16;
            uint32_t qh[2][4], ql[2][4], kh[8][2], kl[8][2];
#pragma unroll
            for (int ma = 0; ma < 2; ma++) {
                uint32_t off = (uint32_t)((w * 32 + ma * 16 + a_r) * (ASTR * 2) +
                                          (kc + a_c) * 2);
                ldsm_x4(qh[ma][0], qh[ma][1], qh[ma][2], qh[ma][3], sb + off);
                ldsm_x4(ql[ma][0], ql[ma][1], ql[ma][2], ql[ma][3],
                        sb + QTILE_B + off);
            }
#pragma unroll
            for (int nb = 0; nb < 4; nb++) {
                uint32_t off = (uint32_t)((nb * 16 + b_r) * (ASTR * 2) +
                                          (kc + b_c) * 2);
                ldsm_x4(kh[2 * nb][0], kh[2 * nb][1],
                        kh[2 * nb + 1][0], kh[2 * nb + 1][1], sKh + off);
                ldsm_x4(kl[2 * nb][0], kl[2 * nb][1],
                        kl[2 * nb + 1][0], kl[2 * nb + 1][1], sKl + off);
            }
#pragma unroll
            for (int ma = 0; ma < 2; ma++)
#pragma unroll
                for (int na = 0; na < 8; na++) {
                    mma_bf16(sc[ma][na], qh[ma], kh[na]);
                    mma_bf16(sc[ma][na], qh[ma], kl[na]);
                    mma_bf16(sc[ma][na], ql[ma], kh[na]);
                }
        }

#pragma unroll
        for (int ma = 0; ma < 2; ma++) {
            float mx0 = -1e30f, mx1 = -1e30f;
#pragma unroll
            for (int na = 0; na < 8; na++) {
#pragma unroll
                for (int r = 0; r < 4; r++) sc[ma][na][r] *= 0.125f;
                mx0 = fmaxf(mx0, fmaxf(sc[ma][na][0], sc[ma][na][1]));
                mx1 = fmaxf(mx1, fmaxf(sc[ma][na][2], sc[ma][na][3]));
            }
            mx0 = fmaxf(mx0, __shfl_xor_sync(0xFFFFFFFFu, mx0, 1));
            mx0 = fmaxf(mx0, __shfl_xor_sync(0xFFFFFFFFu, mx0, 2));
            mx1 = fmaxf(mx1, __shfl_xor_sync(0xFFFFFFFFu, mx1, 1));
            mx1 = fmaxf(mx1, __shfl_xor_sync(0xFFFFFFFFu, mx1, 2));
            float mn0 = fmaxf(m[ma][0], mx0);
            float mn1 = fmaxf(m[ma][1], mx1);
            float c0 = __expf(m[ma][0] - mn0);
            float c1 = __expf(m[ma][1] - mn1);
            float rs0 = 0.f, rs1 = 0.f;
#pragma unroll
            for (int na = 0; na < 8; na++) {
                float p0 = __expf(sc[ma][na][0] - mn0);
                float p1 = __expf(sc[ma][na][1] - mn0);
                float p2 = __expf(sc[ma][na][2] - mn1);
                float p3 = __expf(sc[ma][na][3] - mn1);
                sc[ma][na][0] = p0; sc[ma][na][1] = p1;
                sc[ma][na][2] = p2; sc[ma][na][3] = p3;
                rs0 += p0 + p1;
                rs1 += p2 + p3;
            }
            rs0 += __shfl_xor_sync(0xFFFFFFFFu, rs0, 1);
            rs0 += __shfl_xor_sync(0xFFFFFFFFu, rs0, 2);
            rs1 += __shfl_xor_sync(0xFFFFFFFFu, rs1, 1);
            rs1 += __shfl_xor_sync(0xFFFFFFFFu, rs1, 2);
            l[ma][0] = l[ma][0] * c0 + rs0;
            l[ma][1] = l[ma][1] * c1 + rs1;
            m[ma][0] = mn0;
            m[ma][1] = mn1;
#pragma unroll
            for (int nb = 0; nb < 8; nb++) {
                oa[ma][nb][0] *= c0;
                oa[ma][nb][1] *= c0;
                oa[ma][nb][2] *= c1;
                oa[ma][nb][3] *= c1;
            }
        }

#pragma unroll
        for (int kk = 0; kk < 4; kk++) {
            uint32_t ph[2][4], pl[2][4];
#pragma unroll
            for (int ma = 0; ma < 2; ma++) {
                split2(sc[ma][2 * kk][0],     sc[ma][2 * kk][1],     ph[ma][0], pl[ma][0]);
                split2(sc[ma][2 * kk][2],     sc[ma][2 * kk][3],     ph[ma][1], pl[ma][1]);
                split2(sc[ma][2 * kk + 1][0], sc[ma][2 * kk + 1][1], ph[ma][2], pl[ma][2]);
                split2(sc[ma][2 * kk + 1][2], sc[ma][2 * kk + 1][3], ph[ma][3], pl[ma][3]);
            }
            uint32_t vh[8][2], vl[8][2];
#pragma unroll
            for (int db = 0; db < 4; db++) {
                uint32_t off = (uint32_t)((kk * 16 + a_r) * (ASTR * 2) +
                                          (db * 16 + a_c) * 2);
                ldsm_x4_t(vh[2 * db][0], vh[2 * db][1],
                          vh[2 * db + 1][0], vh[2 * db + 1][1], sVh + off);
                ldsm_x4_t(vl[2 * db][0], vl[2 * db][1],
                          vl[2 * db + 1][0], vl[2 * db + 1][1], sVl + off);
            }
#pragma unroll
            for (int ma = 0; ma < 2; ma++)
#pragma unroll
                for (int nb = 0; nb < 8; nb++) {
                    mma_bf16(oa[ma][nb], ph[ma], vh[nb]);
                    mma_bf16(oa[ma][nb], ph[ma], vl[nb]);
                    mma_bf16(oa[ma][nb], pl[ma], vh[nb]);
                }
        }
        __syncthreads();
    }

#pragma unroll
    for (int ma = 0; ma < 2; ma++) {
#pragma unroll
        for (int half = 0; half < 2; half++) {
            int t = t0 + w * 32 + ma * 16 + half * 8 + (lane >> 2);
            float invl = 1.0f / l[ma][half];
            size_t base = ((size_t)(b * PT + t)) * PD + h * PDK;
#pragma unroll
            for (int nb = 0; nb < 8; nb++) {
                int col = nb * 8 + 2 * (lane & 3);
                float v0 = oa[ma][nb][half * 2 + 0] * invl;
                float v1 = oa[ma][nb][half * 2 + 1] * invl;
                uint32_t hp, lp;
                split2(v0, v1, hp, lp);
                *(uint32_t*)(ohi + base + col) = hp;
                *(uint32_t*)(olo + base + col) = lp;
            }
        }
    }
}

// ---------------------------------------------------------------------------
extern "C" void kernel_launch(void* const* d_in, const int* in_sizes, int n_in,
                              void* d_out, int out_size)
{
    const float* query = (const float*)d_in[0];
    const float* value = (const float*)d_in[1];
    const float* key   = (const float*)d_in[2];
    const float* Wq    = (const float*)d_in[3];
    const float* bq    = (const float*)d_in[4];
    const float* Wk    = (const float*)d_in[5];
    const float* bk    = (const float*)d_in[6];
    const float* Wv    = (const float*)d_in[7];
    const float* bv    = (const float*)d_in[8];
    const float* Wo    = (const float*)d_in[9];
    const float* bo    = (const float*)d_in[10];
    float* out = (float*)d_out;

    __nv_bfloat16 *qhi, *qlo, *khi, *klo, *vhi, *vlo, *ahi, *alo;
    __nv_bfloat16 *pah, *pal, *pbh, *pbl;
    cudaGetSymbolAddress((void**)&qhi, g_qhi);
    cudaGetSymbolAddress((void**)&qlo, g_qlo);
    cudaGetSymbolAddress((void**)&khi, g_khi);
    cudaGetSymbolAddress((void**)&klo, g_klo);
    cudaGetSymbolAddress((void**)&vhi, g_vhi);
    cudaGetSymbolAddress((void**)&vlo, g_vlo);
    cudaGetSymbolAddress((void**)&ahi, g_ahi);
    cudaGetSymbolAddress((void**)&alo, g_alo);
    cudaGetSymbolAddress((void**)&pah, g_pa_hi);
    cudaGetSymbolAddress((void**)&pal, g_pa_lo);
    cudaGetSymbolAddress((void**)&pbh, g_pb_hi);
    cudaGetSymbolAddress((void**)&pbl, g_pb_lo);

    const size_t PA = (size_t)GEMM_M * GEMM_K;   // per-plane A elems
    const size_t PBW = (size_t)GEMM_N * GEMM_K;  // per-plane W elems

    cudaFuncSetAttribute(proj_gemm3_kernel,
                         cudaFuncAttributeMaxDynamicSharedMemorySize, GSM_TOTAL);
    cudaFuncSetAttribute(out_gemm_kernel,
                         cudaFuncAttributeMaxDynamicSharedMemorySize, GSM_TOTAL);
    cudaFuncSetAttribute(attn_mma_kernel,
                         cudaFuncAttributeMaxDynamicSharedMemorySize, AT_SMEM);

    // 1. Split inputs (query, key, value) -> g_pa
    SplitAParams SA;
    SA.x[0] = query; SA.x[1] = key; SA.x[2] = value;
    for (int z = 0; z < 3; z++) {
        SA.hi[z] = pah + z * PA;
        SA.lo[z] = pal + z * PA;
    }
    const int nA4 = GEMM_M * GEMM_K / 4;
    split_a3_kernel<<<dim3((nA4 + 255) / 256, 1, 3), 256>>>(SA, nA4);

    // 2. Split weights (Wq, Wk, Wv, Wo) -> g_pb
    SplitWParams SW;
    SW.w[0] = Wq; SW.w[1] = Wk; SW.w[2] = Wv; SW.w[3] = Wo;
    for (int z = 0; z < 4; z++) {
        SW.hi[z] = pbh + z * PBW;
        SW.lo[z] = pbl + z * PBW;
    }
    split_w4_kernel<<<dim3(GEMM_N / 32, GEMM_K / 32, 4), dim3(32, 8)>>>(SW);

    // 3. Fused Q/K/V projection GEMMs
    ProjParams PP;
    for (int z = 0; z < 3; z++) {
        PP.ah[z] = pah + z * PA;
        PP.al[z] = pal + z * PA;
        PP.bh[z] = pbh + z * PBW;
        PP.bl[z] = pbl + z * PBW;
    }
    PP.bias[0] = bq; PP.bias[1] = bk; PP.bias[2] = bv;
    PP.ch[0] = qhi; PP.cl[0] = qlo;
    PP.ch[1] = khi; PP.cl[1] = klo;
    PP.ch[2] = vhi; PP.cl[2] = vlo;
    proj_gemm3_kernel<<<dim3(GEMM_N / 128, GEMM_M / 128, 3), 256, GSM_TOTAL>>>(PP);

    // 4. Attention -> g_ahi/g_alo (B,T,D)
    attn_mma_kernel<<<dim3(PT / 128, PH, PB), 128, AT_SMEM>>>(
        qhi, qlo, khi, klo, vhi, vlo, ahi, alo);

    // 5. Output projection (fp32 out)
    out_gemm_kernel<<<dim3(GEMM_N / 128, GEMM_M / 128), 256, GSM_TOTAL>>>(
        ahi, alo, pbh + 3 * PBW, pbl + 3 * PBW, bo, out);
}